// round 5
// baseline (speedup 1.0000x reference)
#include <cuda_runtime.h>
#include <cstdint>

// Problem constants
#define B_    4096
#define T_    512
#define D_    64
#define H_    128
#define A_    8

#define CLSZ  4       // CTAs per cluster
#define BB    128     // batch rows per cluster
#define JH    32      // hidden units per CTA (4 CTAs cover H=128)
#define NTHR  512     // 16 warps; warp w owns CTA-local j pair [2w, 2w+2)
#define KTOT  192     // fused K: 64 (x_t) + 128 (h)

// Dynamic smem layout:
//   Ws : [192 k][4 g][32 j]  fp32 -> 24576 floats (98304 B)
//   act: [192 k][128 b]      fp32 -> rows 0..63 = x_t[d][b], 64..191 = h[j][b]
#define W_ELEMS    (KTOT * 4 * JH)
#define ACT_ELEMS  (KTOT * BB)
#define SMEM_BYTES ((W_ELEMS + ACT_ELEMS) * 4)   // 196608 B

// ----------------- helpers -----------------

__device__ __forceinline__ uint32_t s2u(const void* p) {
    uint32_t a;
    asm("{ .reg .u64 t; cvta.to.shared.u64 t, %1; cvt.u32.u64 %0, t; }"
        : "=r"(a) : "l"(p));
    return a;
}

__device__ __forceinline__ void cluster_sync_() {
    asm volatile("barrier.cluster.arrive.aligned;" ::: "memory");
    asm volatile("barrier.cluster.wait.aligned;" ::: "memory");
}

__device__ __forceinline__ unsigned long long pack2(float x, float y) {
    unsigned long long r;
    asm("mov.b64 %0, {%1, %2};" : "=l"(r) : "f"(x), "f"(y));
    return r;
}
__device__ __forceinline__ void unpack2(unsigned long long v, float& x, float& y) {
    asm("mov.b64 {%0, %1}, %2;" : "=f"(x), "=f"(y) : "l"(v));
}

// fast, overflow-safe sigmoid / tanh (~1e-6 accuracy, MUFU-based)
__device__ __forceinline__ float sigf(float x) {
    return __fdividef(1.0f, 1.0f + __expf(-x));
}
__device__ __forceinline__ float tanh_f(float x) {
    float e = __expf(-2.0f * fabsf(x));
    float r = __fdividef(1.0f - e, 1.0f + e);
    return copysignf(r, x);
}

// One broadcast weight-pair load feeding 4 batch columns (4 FFMA2).
// wk already includes this warp's j-pair byte offset (warp*2*4).
#define WFMA(g)                                                                     \
    {                                                                               \
        unsigned long long wv;                                                      \
        asm volatile("ld.shared.b64 %0, [%1+%2];"                                   \
                     : "=l"(wv) : "r"(wk), "n"((g) * JH * 4));                      \
        asm("fma.rn.f32x2 %0, %1, %2, %0;" : "+l"(acc[(g)*4+0]) : "l"(wv), "l"(av0)); \
        asm("fma.rn.f32x2 %0, %1, %2, %0;" : "+l"(acc[(g)*4+1]) : "l"(wv), "l"(av1)); \
        asm("fma.rn.f32x2 %0, %1, %2, %0;" : "+l"(acc[(g)*4+2]) : "l"(wv), "l"(av2)); \
        asm("fma.rn.f32x2 %0, %1, %2, %0;" : "+l"(acc[(g)*4+3]) : "l"(wv), "l"(av3)); \
    }

union F4 { float4 v; float f[4]; };

__global__ void __launch_bounds__(NTHR, 1) __cluster_dims__(CLSZ, 1, 1)
lstm_fused_kernel(const float* __restrict__ state,   // [B, T, D]
                  const float* __restrict__ W_ih,    // [4H, D]
                  const float* __restrict__ W_hh,    // [4H, H]
                  const float* __restrict__ b_ih,    // [4H]
                  const float* __restrict__ b_hh,    // [4H]
                  const float* __restrict__ W_fc,    // [A, H]
                  const float* __restrict__ b_fc,    // [A]
                  float* __restrict__ out)           // [B, A]
{
    extern __shared__ float smem[];
    float* Ws  = smem;               // [(k*4 + g)*32 + jl]
    float* act = smem + W_ELEMS;     // [k*128 + b]

    const int tid  = threadIdx.x;
    const int lane = tid & 31;
    const int warp = tid >> 5;       // 0..15
    const int jb   = warp * 2;       // CTA-local j pair base
    const int d0   = warp * 4;       // x-dims owned for load/store
    const int bloc = lane * 4;       // this thread's 4 batch columns [bloc, bloc+4)

    uint32_t rank;
    asm("mov.u32 %0, %%cluster_ctarank;" : "=r"(rank));
    const int b0  = (blockIdx.x >> 2) * BB;   // cluster's global batch base
    const int jg0 = (int)rank * JH;           // this CTA's global j offset

    // ---- Fill Ws (coalesced over k in global memory) ----
    for (int e = tid; e < 4 * JH * D_; e += NTHR) {       // x-part k in [0,64)
        int k  = e & 63;
        int rl = e >> 6;
        int g  = rl >> 5;
        int jl = rl & 31;
        Ws[(k * 4 + g) * JH + jl] = W_ih[(g * H_ + jg0 + jl) * D_ + k];
    }
    for (int e = tid; e < 4 * JH * H_; e += NTHR) {       // h-part k in [64,192)
        int k  = e & 127;
        int rl = e >> 7;
        int g  = rl >> 5;
        int jl = rl & 31;
        Ws[((64 + k) * 4 + g) * JH + jl] = W_hh[(g * H_ + jg0 + jl) * H_ + k];
    }

    // ---- init act: h rows (64..191) = 0 ----
    for (int e = tid; e < H_ * BB; e += NTHR)
        act[(D_ + (e >> 7)) * BB + (e & 127)] = 0.0f;

    // ---- x_0 into act rows 0..63 ----
    {
        F4 x[4];
#pragma unroll
        for (int q = 0; q < 4; q++)
            x[q].v = *(const float4*)(state + (size_t)(b0 + bloc + q) * T_ * D_ + d0);
#pragma unroll
        for (int i = 0; i < 4; i++)
            *(float4*)(act + (d0 + i) * BB + bloc) =
                make_float4(x[0].f[i], x[1].f[i], x[2].f[i], x[3].f[i]);
    }

    // ---- bias preload (per g, for this warp's j pair; column-independent) ----
    unsigned long long bias2[4];
#pragma unroll
    for (int g = 0; g < 4; g++) {
        int r = g * H_ + jg0 + jb;
        bias2[g] = pack2(b_ih[r] + b_hh[r], b_ih[r + 1] + b_hh[r + 1]);
    }

    float c[8];   // [q*2 + jj]
#pragma unroll
    for (int i = 0; i < 8; i++) c[i] = 0.0f;

    const uint32_t act_u = s2u(act);
    const uint32_t W_u   = s2u(Ws);
    const uint32_t ak0   = act_u + (uint32_t)bloc * 4;     // + lane*16
    const uint32_t wk0   = W_u + (uint32_t)jb * 4;
    // local h-store base: row (64 + jg0 + jb), cols bloc..bloc+3
    const uint32_t h0addr = act_u + (uint32_t)(D_ + jg0 + jb) * BB * 4 + (uint32_t)bloc * 4;

    __syncthreads();   // Ws/act init visible CTA-locally (first step reads local only)

    for (int t = 0; t < T_; t++) {
        // prefetch x_{t+1} into registers (consumed after cluster sync #1)
        F4 xp[4];
        if (t < T_ - 1) {
#pragma unroll
            for (int q = 0; q < 4; q++)
                xp[q].v = *(const float4*)(state + (size_t)(b0 + bloc + q) * T_ * D_
                                           + (t + 1) * D_ + d0);
        }

        // ---- gates = Ws^T * act + bias (2 j x 4 g x 4 cols per thread) ----
        unsigned long long acc[16];
#pragma unroll
        for (int g = 0; g < 4; g++) {
            acc[g * 4 + 0] = bias2[g];
            acc[g * 4 + 1] = bias2[g];
            acc[g * 4 + 2] = bias2[g];
            acc[g * 4 + 3] = bias2[g];
        }

        uint32_t ak = ak0, wk = wk0;
#pragma unroll 4
        for (int k = 0; k < KTOT; k++) {
            float a0, a1, a2, a3;
            asm volatile("ld.shared.v4.f32 {%0,%1,%2,%3}, [%4];"
                         : "=f"(a0), "=f"(a1), "=f"(a2), "=f"(a3) : "r"(ak));
            unsigned long long av0 = pack2(a0, a0);
            unsigned long long av1 = pack2(a1, a1);
            unsigned long long av2 = pack2(a2, a2);
            unsigned long long av3 = pack2(a3, a3);
            WFMA(0) WFMA(1) WFMA(2) WFMA(3)
            ak += BB * 4;        // 512 B per k row
            wk += 4 * JH * 4;    // 512 B per k row
        }

        // ---- activations: i,f,g,o -> c, h ----
        float hv[8];   // [q*2 + jj]
#pragma unroll
        for (int q = 0; q < 4; q++) {
            float i0, i1, f0, f1, g0, g1, o0, o1;
            unpack2(acc[0 * 4 + q], i0, i1);
            unpack2(acc[1 * 4 + q], f0, f1);
            unpack2(acc[2 * 4 + q], g0, g1);
            unpack2(acc[3 * 4 + q], o0, o1);
            {
                float cn = sigf(f0) * c[q * 2 + 0] + sigf(i0) * tanh_f(g0);
                c[q * 2 + 0]  = cn;
                hv[q * 2 + 0] = sigf(o0) * tanh_f(cn);
            }
            {
                float cn = sigf(f1) * c[q * 2 + 1] + sigf(i1) * tanh_f(g1);
                c[q * 2 + 1]  = cn;
                hv[q * 2 + 1] = sigf(o1) * tanh_f(cn);
            }
        }

        cluster_sync_();   // #1: all CTAs done READING act

        // ---- store my h (2 j x 4 cols): local v4 + 3 remote peers (scalar) ----
#pragma unroll
        for (int jj = 0; jj < 2; jj++) {
            uint32_t addr = h0addr + (uint32_t)jj * BB * 4;
            asm volatile("st.shared.v4.f32 [%0], {%1,%2,%3,%4};"
                         :: "r"(addr), "f"(hv[0 * 2 + jj]), "f"(hv[1 * 2 + jj]),
                            "f"(hv[2 * 2 + jj]), "f"(hv[3 * 2 + jj]) : "memory");
        }
#pragma unroll
        for (int pr = 0; pr < CLSZ; pr++) {
            if (pr == (int)rank) continue;
            uint32_t ra;
            asm volatile("mapa.shared::cluster.u32 %0, %1, %2;"
                         : "=r"(ra) : "r"(h0addr), "r"((uint32_t)pr));
#pragma unroll
            for (int jj = 0; jj < 2; jj++) {
#pragma unroll
                for (int q = 0; q < 4; q++) {
                    asm volatile("st.shared::cluster.f32 [%0], %1;"
                                 :: "r"(ra + (uint32_t)(jj * BB * 4 + q * 4)),
                                    "f"(hv[q * 2 + jj]) : "memory");
                }
            }
        }

        // ---- store x_{t+1} ----
        if (t < T_ - 1) {
#pragma unroll
            for (int i = 0; i < 4; i++)
                *(float4*)(act + (d0 + i) * BB + bloc) =
                    make_float4(xp[0].f[i], xp[1].f[i], xp[2].f[i], xp[3].f[i]);
        }

        cluster_sync_();   // #2: all writes (incl. remote h) visible before next read
    }

    // ---- FC epilogue: out = tanh(h @ W_fc^T + b_fc) ----
    // act rows 64..191 hold final h for all 128 units x all 128 cluster batches.
    // CTA rank handles batch cols [rank*32, rank*32+32); warps 0..7 -> a = warp.
    if (warp < A_) {
        int a   = warp;
        int col = (int)rank * 32 + lane;
        float s = b_fc[a];
        const float* wf = W_fc + a * H_;
#pragma unroll 8
        for (int j = 0; j < H_; j++)
            s += act[(D_ + j) * BB + col] * wf[j];
        out[(size_t)(b0 + col) * A_ + a] = tanhf(s);
    }
}

extern "C" void kernel_launch(void* const* d_in, const int* in_sizes, int n_in,
                              void* d_out, int out_size) {
    (void)in_sizes; (void)n_in; (void)out_size;
    cudaFuncSetAttribute(lstm_fused_kernel,
                         cudaFuncAttributeMaxDynamicSharedMemorySize, SMEM_BYTES);
    const float* state = (const float*)d_in[0];
    const float* W_ih  = (const float*)d_in[1];
    const float* W_hh  = (const float*)d_in[2];
    const float* b_ih  = (const float*)d_in[3];
    const float* b_hh  = (const float*)d_in[4];
    const float* W_fc  = (const float*)d_in[5];
    const float* b_fc  = (const float*)d_in[6];

    dim3 grid((B_ / BB) * CLSZ);   // 128 CTAs = 32 clusters of 4 -> single wave
    lstm_fused_kernel<<<grid, NTHR, SMEM_BYTES>>>(
        state, W_ih, W_hh, b_ih, b_hh, W_fc, b_fc, (float*)d_out);
}